// round 16
// baseline (speedup 1.0000x reference)
#include <cuda_runtime.h>
#include <cstdint>
#include <math.h>

#define T_TOK 2048
#define HD    2048
#define ID    768
#define NE    32
#define TOPK  4
#define NPAIR (T_TOK*TOPK)
#define MAXT  96
#define NPAD  (MAXT*128)

// ---------------- scratch ----------------
__device__ int   g_cnt[NE];
__device__ int   g_tk_id[NPAIR];
__device__ float g_tk_w[NPAIR];
__device__ int   g_slot[NPAIR];
__device__ int   g_pair_tok[NPAD];
__device__ float g_pair_w[NPAD];
__device__ int   g_tile_e[MAXT];
__device__ int   g_tile_base[MAXT];
__device__ int   g_ntile;
__device__ float g_xtf[(size_t)T_TOK * HD];          // X pre-rounded to tf32
__device__ float g_act[(size_t)NPAD * ID];           // stage-A out, tf32-rounded
__device__ float g_pairout[(size_t)NPAD * HD];

// ---------------- helpers ----------------
__device__ __forceinline__ uint32_t smem_u32(const void* p) {
    uint32_t a;
    asm("{ .reg .u64 t; cvta.to.shared.u64 t, %1; cvt.u32.u64 %0, t; }" : "=r"(a) : "l"(p));
    return a;
}
__device__ __forceinline__ uint32_t tf32r(float f) {
    uint32_t u; asm("cvt.rna.tf32.f32 %0, %1;" : "=r"(u) : "f"(f)); return u;
}
__device__ __forceinline__ void cpasync16(uint32_t dst, const void* src) {
    asm volatile("cp.async.cg.shared.global [%0], [%1], 16;" :: "r"(dst), "l"(src));
}
#define CP_COMMIT() asm volatile("cp.async.commit_group;" ::: "memory")
#define CP_WAIT1()  asm volatile("cp.async.wait_group 1;" ::: "memory")
#define CP_WAIT0()  asm volatile("cp.async.wait_group 0;" ::: "memory")

__device__ __forceinline__ void mma8(float* c, const uint32_t* a, const uint32_t* b) {
    asm volatile("mma.sync.aligned.m16n8k8.row.col.f32.tf32.tf32.f32 "
        "{%0,%1,%2,%3}, {%4,%5,%6,%7}, {%8,%9}, {%0,%1,%2,%3};"
        : "+f"(c[0]), "+f"(c[1]), "+f"(c[2]), "+f"(c[3])
        : "r"(a[0]), "r"(a[1]), "r"(a[2]), "r"(a[3]), "r"(b[0]), "r"(b[1]));
}
#define LDSM4(r0,r1,r2,r3,addr) \
    asm volatile("ldmatrix.sync.aligned.m8n8.x4.shared.b16 {%0,%1,%2,%3}, [%4];" \
        : "=r"(r0), "=r"(r1), "=r"(r2), "=r"(r3) : "r"(addr))

#define ASTR 36     // A smem row stride (floats): 144B = 9x16B -> LDSM conflict-free
#define BSTR 72     // B smem k-row stride (floats): 72 mod 32 = 8 -> scalar LDS conflict-free
// floats: sA0 0, sA1 4608, sB0 9216, sB1 11520, wts 13824, end 13952
#define OFF_SA1 4608
#define OFF_SB0 9216
#define OFF_SB1 11520
#define OFF_WTS 13824
#define SM_BYTES (13952 * 4)   // 55808 B/block -> 3 blocks/SM fits 227KB

// ---------------- launch #0: cvt X to tf32 AND zero pair lists/counters ----------------
__global__ void zerocvt_kernel(const float* __restrict__ x) {
    int i = blockIdx.x * 256 + threadIdx.x;
    float4 v = ((const float4*)x)[i];
    float4 o = make_float4(__uint_as_float(tf32r(v.x)), __uint_as_float(tf32r(v.y)),
                           __uint_as_float(tf32r(v.z)), __uint_as_float(tf32r(v.w)));
    ((float4*)g_xtf)[i] = o;
    if (i < NPAD) { g_pair_tok[i] = 0; g_pair_w[i] = 0.f; }
    if (i < NE) g_cnt[i] = 0;
}

// ---------------- launch #1: router ----------------
__global__ void router_kernel(const float* __restrict__ x, const float* __restrict__ gw) {
    __shared__ float xs[HD];
    __shared__ float lg[NE];
    int t = blockIdx.x;
    const float4* xv  = (const float4*)(x + (size_t)t * HD);
    float4*       xsv = (float4*)xs;
    for (int i = threadIdx.x; i < HD/4; i += blockDim.x) xsv[i] = xv[i];
    __syncthreads();
    int warp = threadIdx.x >> 5, lane = threadIdx.x & 31;
    for (int e = warp; e < NE; e += 8) {
        const float4* w = (const float4*)(gw + (size_t)e * HD);
        float s = 0.f;
        #pragma unroll 4
        for (int h = lane; h < HD/4; h += 32) {
            float4 wv = w[h]; float4 xr = xsv[h];
            s += wv.x*xr.x + wv.y*xr.y + wv.z*xr.z + wv.w*xr.w;
        }
        #pragma unroll
        for (int o = 16; o; o >>= 1) s += __shfl_xor_sync(0xffffffffu, s, o);
        if (lane == 0) lg[e] = s;
    }
    __syncthreads();
    if (threadIdx.x == 0) {
        int sel[TOPK]; float sv[TOPK];
        unsigned used = 0u;
        #pragma unroll
        for (int k = 0; k < TOPK; k++) {
            float best = -1e30f; int bi = 0;
            for (int e2 = 0; e2 < NE; e2++)
                if (!((used >> e2) & 1u) && lg[e2] > best) { best = lg[e2]; bi = e2; }
            used |= 1u << bi; sel[k] = bi; sv[k] = best;
        }
        float mx = sv[0], den = 0.f, ww[TOPK];
        #pragma unroll
        for (int k = 0; k < TOPK; k++) { ww[k] = expf(sv[k] - mx); den += ww[k]; }
        #pragma unroll
        for (int k = 0; k < TOPK; k++) {
            g_tk_id[t*TOPK + k] = sel[k];
            g_tk_w [t*TOPK + k] = ww[k] / den;
            atomicAdd(&g_cnt[sel[k]], 1);
        }
    }
}

// ---------------- launch #2: scan + pad-tile build + pair fill, one block ----------------
__global__ void scanfill_kernel() {
    __shared__ int scur[NE];
    int tid = threadIdx.x;
    if (tid < 32) {
        int lane = tid;
        int c = (lane < NE) ? g_cnt[lane] : 0;
        int tiles = (c + 127) >> 7;
        int pad = tiles * 128;
        int poff = pad, toff = tiles;
        #pragma unroll
        for (int o = 1; o < 32; o <<= 1) {
            int pv = __shfl_up_sync(0xffffffffu, poff, o);
            int tv = __shfl_up_sync(0xffffffffu, toff, o);
            if (lane >= o) { poff += pv; toff += tv; }
        }
        int pbase = poff - pad, tbase = toff - tiles;
        if (lane < NE) {
            scur[lane] = pbase;
            for (int i = 0; i < tiles; i++) {
                g_tile_e[tbase + i] = lane;
                g_tile_base[tbase + i] = pbase + i*128;
            }
        }
        if (lane == 31) g_ntile = toff;
    }
    __syncthreads();
    for (int p = tid; p < NPAIR; p += 256) {
        int e = g_tk_id[p];
        int pos = atomicAdd(&scur[e], 1);
        g_pair_tok[pos] = p >> 2;
        g_pair_w [pos] = g_tk_w[p];
        g_slot[p] = pos;
    }
}

// ---------------- launch #5: combine ----------------
__global__ void combine_kernel(float* __restrict__ out) {
    int t = blockIdx.x;
    int s0 = g_slot[t*4+0], s1 = g_slot[t*4+1], s2 = g_slot[t*4+2], s3 = g_slot[t*4+3];
    const float4* p0 = (const float4*)(g_pairout + (size_t)s0 * HD);
    const float4* p1 = (const float4*)(g_pairout + (size_t)s1 * HD);
    const float4* p2 = (const float4*)(g_pairout + (size_t)s2 * HD);
    const float4* p3 = (const float4*)(g_pairout + (size_t)s3 * HD);
    float4* o = (float4*)(out + (size_t)t * HD);
    for (int i = threadIdx.x; i < HD/4; i += 256) {
        float4 a = p0[i], b = p1[i], c = p2[i], d = p3[i];
        o[i] = make_float4(a.x+b.x+c.x+d.x, a.y+b.y+c.y+d.y,
                           a.z+b.z+c.z+d.z, a.w+b.w+c.w+d.w);
    }
}

// ---------------- launch #3: stage A — 256 thr, 8 warps 2m x 4n, warp tile m64 x n8-logical ----------------
__global__ void __launch_bounds__(256, 3)
stageA_kernel(const float* __restrict__ Wg, const float* __restrict__ Wu) {
    int mt = blockIdx.y;
    if (mt >= g_ntile) return;
    int e = g_tile_e[mt], base = g_tile_base[mt];
    int nb = blockIdx.x;  // 32 logical I cols per block

    extern __shared__ float sm[];
    float* sB[2] = { sm + OFF_SB0, sm + OFF_SB1 };
    float* wts = sm + OFF_WTS;
    uint32_t sAu[2] = { smem_u32(sm), smem_u32(sm + OFF_SA1) };
    uint32_t sBu[2] = { smem_u32(sB[0]), smem_u32(sB[1]) };

    int t = threadIdx.x;
    if (t < 128) wts[t] = g_pair_w[base + t];

    // A producer: thread -> (row, 64B half); 4x16B per thread
    int arow = t >> 1, aseg = t & 1;
    const float* asrc0 = g_xtf + (size_t)g_pair_tok[base + arow] * HD + aseg * 16;
    uint32_t adst = (uint32_t)(arow * (ASTR*4) + aseg * 64);
    // B producer: thread -> (k0 0..15, 16B col chunk 0..15); 2 k-rows per thread
    // phys cols: 0-31 = Wg[nb*32..], 32-63 = Wu[nb*32..]
    int bc = t & 15, bk0 = t >> 4;
    const float* Wge = Wg + (size_t)e * HD * ID + (size_t)nb * 32;
    const float* Wue = Wu + (size_t)e * HD * ID + (size_t)nb * 32;
    const float* bsrc0 = ((bc < 8) ? (Wge + bc*4) : (Wue + (bc-8)*4)) + (size_t)bk0 * ID;
    uint32_t bdst = (uint32_t)(bk0 * (BSTR*4) + bc * 16);

    int lane = t & 31, wid = t >> 5;
    int wm  = (wid & 1) * 64;        // 2 m-warp groups
    int wng = (wid >> 1) * 8;        // 4 logical-n warp groups (8 cols each)
    int grp = lane >> 2, tg = lane & 3;
    uint32_t aoff = (uint32_t)((wm + (lane & 15)) * (ASTR*4) + (lane >> 4) * 16);

    float acc[4][2][4];   // [mfrag][g,u][frag]
    #pragma unroll
    for (int m = 0; m < 4; m++)
        #pragma unroll
        for (int n = 0; n < 2; n++)
            #pragma unroll
            for (int i = 0; i < 4; i++) acc[m][n][i] = 0.f;

    #pragma unroll
    for (int i = 0; i < 4; i++) cpasync16(sAu[0] + adst + i*16, asrc0 + i*4);
    #pragma unroll
    for (int i = 0; i < 2; i++) cpasync16(sBu[0] + bdst + i*16*(BSTR*4), bsrc0 + (size_t)i*16*ID);
    CP_COMMIT();

    for (int kc = 0; kc < 64; kc++) {
        int b = kc & 1;
        __syncthreads();
        if (kc + 1 < 64) {
            const float* as = asrc0 + (size_t)(kc+1) * 32;
            const float* bs = bsrc0 + (size_t)(kc+1) * 32 * ID;
            #pragma unroll
            for (int i = 0; i < 4; i++) cpasync16(sAu[b^1] + adst + i*16, as + i*4);
            #pragma unroll
            for (int i = 0; i < 2; i++) cpasync16(sBu[b^1] + bdst + i*16*(BSTR*4), bs + (size_t)i*16*ID);
            CP_COMMIT();
            CP_WAIT1();
        } else {
            CP_WAIT0();
        }
        __syncthreads();

        uint32_t abase = sAu[b] + aoff;
        const float* B = sB[b];
        #pragma unroll
        for (int ks = 0; ks < 4; ks++) {
            uint32_t af[4][4];
            #pragma unroll
            for (int m = 0; m < 4; m++)
                LDSM4(af[m][0], af[m][1], af[m][2], af[m][3], abase + m*(16*ASTR*4) + ks*32);
            int k = ks*8 + tg;
            int colg = wng + grp;
            uint32_t bf[2];
            bf[0] = tf32r(B[k*BSTR + colg]);
            bf[1] = tf32r(B[(k+4)*BSTR + colg]);
            #pragma unroll
            for (int m = 0; m < 4; m++) mma8(acc[m][0], af[m], bf);
            bf[0] = tf32r(B[k*BSTR + 32 + colg]);
            bf[1] = tf32r(B[(k+4)*BSTR + 32 + colg]);
            #pragma unroll
            for (int m = 0; m < 4; m++) mma8(acc[m][1], af[m], bf);
        }
    }

    // epilogue: silu(g)*u*wt, round to tf32, float2 stores
    #pragma unroll
    for (int m = 0; m < 4; m++) {
        int r0 = wm + m*16 + grp, r1 = r0 + 8;
        float w0 = wts[r0], w1 = wts[r1];
        int icol = nb*32 + wng + 2*tg;
        float g0 = acc[m][0][0], g1 = acc[m][0][1];
        float g2 = acc[m][0][2], g3 = acc[m][0][3];
        float u0 = acc[m][1][0], u1 = acc[m][1][1];
        float u2 = acc[m][1][2], u3 = acc[m][1][3];
        float v0 = g0 / (1.f + __expf(-g0)) * u0 * w0;
        float v1 = g1 / (1.f + __expf(-g1)) * u1 * w0;
        float v2 = g2 / (1.f + __expf(-g2)) * u2 * w1;
        float v3 = g3 / (1.f + __expf(-g3)) * u3 * w1;
        *(float2*)(g_act + (size_t)(base + r0) * ID + icol) =
            make_float2(__uint_as_float(tf32r(v0)), __uint_as_float(tf32r(v1)));
        *(float2*)(g_act + (size_t)(base + r1) * ID + icol) =
            make_float2(__uint_as_float(tf32r(v2)), __uint_as_float(tf32r(v3)));
    }
}

// ---------------- launch #4: stage B — 256 thr, 8 warps 2m x 4n, warp tile m64 x n16 ----------------
__global__ void __launch_bounds__(256, 3)
stageB_kernel(const float* __restrict__ Wd) {
    int mt = blockIdx.y;
    if (mt >= g_ntile) return;
    int e = g_tile_e[mt], base = g_tile_base[mt];
    int nb = blockIdx.x;  // 64 HD cols per block

    extern __shared__ float sm[];
    float* sB[2] = { sm + OFF_SB0, sm + OFF_SB1 };
    uint32_t sAu[2] = { smem_u32(sm), smem_u32(sm + OFF_SA1) };
    uint32_t sBu[2] = { smem_u32(sB[0]), smem_u32(sB[1]) };

    int t = threadIdx.x;
    int arow = t >> 1, aseg = t & 1;
    const float* asrc0 = g_act + (size_t)(base + arow) * ID + aseg * 16;
    uint32_t adst = (uint32_t)(arow * (ASTR*4) + aseg * 64);
    int bc = t & 15, bk0 = t >> 4;
    const float* We = Wd + (size_t)e * ID * HD + (size_t)nb * 64;
    const float* bsrc0 = We + bc*4 + (size_t)bk0 * HD;
    uint32_t bdst = (uint32_t)(bk0 * (BSTR*4) + bc * 16);

    int lane = t & 31, wid = t >> 5;
    int wm = (wid & 1) * 64;
    int wn = (wid >> 1) * 16;
    int grp = lane >> 2, tg = lane & 3;
    uint32_t aoff = (uint32_t)((wm + (lane & 15)) * (ASTR*4) + (lane >> 4) * 16);

    float acc[4][2][4];
    #pragma unroll
    for (int m = 0; m < 4; m++)
        #pragma unroll
        for (int n = 0; n < 2; n++)
            #pragma unroll
            for (int i = 0; i < 4; i++) acc[m][n][i] = 0.f;

    #pragma unroll
    for (int i = 0; i < 4; i++) cpasync16(sAu[0] + adst + i*16, asrc0 + i*4);
    #pragma unroll
    for (int i = 0; i < 2; i++) cpasync16(sBu[0] + bdst + i*16*(BSTR*4), bsrc0 + (size_t)i*16*HD);
    CP_COMMIT();

    for (int kc = 0; kc < 24; kc++) {
        int b = kc & 1;
        __syncthreads();
        if (kc + 1 < 24) {
            const float* as = asrc0 + (size_t)(kc+1) * 32;
            const float* bs = bsrc0 + (size_t)(kc+1) * 32 * HD;
            #pragma unroll
            for (int i = 0; i < 4; i++) cpasync16(sAu[b^1] + adst + i*16, as + i*4);
            #pragma unroll
            for (int i = 0; i < 2; i++) cpasync16(sBu[b^1] + bdst + i*16*(BSTR*4), bs + (size_t)i*16*HD);
            CP_COMMIT();
            CP_WAIT1();
        } else {
            CP_WAIT0();
        }
        __syncthreads();

        uint32_t abase = sAu[b] + aoff;
        const float* B = sB[b];
        #pragma unroll
        for (int ks = 0; ks < 4; ks++) {
            uint32_t af[4][4];
            #pragma unroll
            for (int m = 0; m < 4; m++)
                LDSM4(af[m][0], af[m][1], af[m][2], af[m][3], abase + m*(16*ASTR*4) + ks*32);
            int k = ks*8 + tg;
            #pragma unroll
            for (int n = 0; n < 2; n++) {
                int col = wn + n*8 + grp;
                uint32_t bf[2];
                bf[0] = tf32r(B[k*BSTR + col]);
                bf[1] = tf32r(B[(k+4)*BSTR + col]);
                #pragma unroll
                for (int m = 0; m < 4; m++) mma8(acc[m][n], af[m], bf);
            }
        }
    }

    #pragma unroll
    for (int m = 0; m < 4; m++) {
        int r0 = wm + m*16 + grp, r1 = r0 + 8;
        #pragma unroll
        for (int n = 0; n < 2; n++) {
            int col = nb*64 + wn + n*8 + 2*tg;
            *(float2*)(g_pairout + (size_t)(base + r0) * HD + col) =
                make_float2(acc[m][n][0], acc[m][n][1]);
            *(float2*)(g_pairout + (size_t)(base + r1) * HD + col) =
                make_float2(acc[m][n][2], acc[m][n][3]);
        }
    }
}

// ---------------- launch ----------------
extern "C" void kernel_launch(void* const* d_in, const int* in_sizes, int n_in,
                              void* d_out, int out_size) {
    const float* x  = (const float*)d_in[0];
    const float* gw = (const float*)d_in[1];
    const float* Wg = (const float*)d_in[2];
    const float* Wu = (const float*)d_in[3];
    const float* Wd = (const float*)d_in[4];
    float* out = (float*)d_out;

    cudaFuncSetAttribute(stageA_kernel, cudaFuncAttributeMaxDynamicSharedMemorySize, SM_BYTES);
    cudaFuncSetAttribute(stageB_kernel, cudaFuncAttributeMaxDynamicSharedMemorySize, SM_BYTES);

    zerocvt_kernel<<<(T_TOK*HD/4)/256, 256>>>(x);                 // 0: cvt X + zero pairs/counters
    router_kernel<<<T_TOK, 256>>>(x, gw);                         // 1
    scanfill_kernel<<<1, 256>>>();                                // 2: scan+pad+fill
    stageA_kernel<<<dim3(ID/32, MAXT), 256, SM_BYTES>>>(Wg, Wu);  // 3 <- profiled by ncu
    stageB_kernel<<<dim3(HD/64, MAXT), 256, SM_BYTES>>>(Wd);      // 4
    combine_kernel<<<T_TOK, 256>>>(out);                          // 5
}

// round 17
// speedup vs baseline: 1.5381x; 1.5381x over previous
#include <cuda_runtime.h>
#include <cuda_fp16.h>
#include <cstdint>
#include <math.h>

#define T_TOK 2048
#define HD    2048
#define ID    768
#define NE    32
#define TOPK  4
#define NPAIR (T_TOK*TOPK)
#define MAXT  96
#define NPAD  (MAXT*128)
#define WN    (NE*HD*ID)

// ---------------- scratch ----------------
__device__ int   g_cnt[NE];
__device__ int   g_tk_id[NPAIR];
__device__ float g_tk_w[NPAIR];
__device__ int   g_slot[NPAIR];
__device__ int   g_pair_tok[NPAD];
__device__ float g_pair_w[NPAD];
__device__ int   g_tile_e[MAXT];
__device__ int   g_tile_base[MAXT];
__device__ int   g_ntile;
__device__ __align__(16) __half g_xh[(size_t)T_TOK * HD];    // X in fp16
__device__ __align__(16) __half g_wgh[(size_t)WN];           // Wg fp16
__device__ __align__(16) __half g_wuh[(size_t)WN];           // Wu fp16
__device__ __align__(16) __half g_wdh[(size_t)WN];           // Wd fp16
__device__ __align__(16) __half g_act_h[(size_t)NPAD * ID];  // stage-A out fp16
__device__ float g_pairout[(size_t)NPAD * HD];

// ---------------- helpers ----------------
__device__ __forceinline__ uint32_t smem_u32(const void* p) {
    uint32_t a;
    asm("{ .reg .u64 t; cvta.to.shared.u64 t, %1; cvt.u32.u64 %0, t; }" : "=r"(a) : "l"(p));
    return a;
}
__device__ __forceinline__ void cpasync16(uint32_t dst, const void* src) {
    asm volatile("cp.async.cg.shared.global [%0], [%1], 16;" :: "r"(dst), "l"(src));
}
#define CP_COMMIT() asm volatile("cp.async.commit_group;" ::: "memory")
#define CP_WAIT1()  asm volatile("cp.async.wait_group 1;" ::: "memory")
#define CP_WAIT0()  asm volatile("cp.async.wait_group 0;" ::: "memory")

__device__ __forceinline__ void mma16(float* c, const uint32_t* a, const uint32_t* b) {
    asm volatile("mma.sync.aligned.m16n8k16.row.col.f32.f16.f16.f32 "
        "{%0,%1,%2,%3}, {%4,%5,%6,%7}, {%8,%9}, {%0,%1,%2,%3};"
        : "+f"(c[0]), "+f"(c[1]), "+f"(c[2]), "+f"(c[3])
        : "r"(a[0]), "r"(a[1]), "r"(a[2]), "r"(a[3]), "r"(b[0]), "r"(b[1]));
}
#define LDSM4(r0,r1,r2,r3,addr) \
    asm volatile("ldmatrix.sync.aligned.m8n8.x4.shared.b16 {%0,%1,%2,%3}, [%4];" \
        : "=r"(r0), "=r"(r1), "=r"(r2), "=r"(r3) : "r"(addr))
#define LDSMT2(r0,r1,addr) \
    asm volatile("ldmatrix.sync.aligned.m8n8.x2.trans.shared.b16 {%0,%1}, [%2];" \
        : "=r"(r0), "=r"(r1) : "r"(addr))

// A smem: [128 rows][40 halves] (80B rows, 16B-aligned, LDSM conflict-free)
// B smem: [32 k-rows][136 halves] (272B rows, 16B-aligned, LDSM.trans conflict-free)
#define AROWB 80
#define BROWB 272
// bytes: sA0 0, sA1 10240, sB0 20480, sB1 29184, wts 37888..38400
#define OFF_SA1B 10240
#define OFF_SB0B 20480
#define OFF_SB1B 29184
#define OFF_WTSB 37888
#define SM_BYTES 38400

// ---------------- launch #0: prep — cvt X & weights to fp16, zero pairs/counters ----------------
__global__ void prep_kernel(const float* __restrict__ x, const float* __restrict__ Wg,
                            const float* __restrict__ Wu, const float* __restrict__ Wd) {
    long gid = (long)blockIdx.x * 256 + threadIdx.x;
    const long X8 = (long)T_TOK * HD / 8;    // 524288
    const long W8 = (long)WN / 8;            // 6291456
    const float* src; __half* dst; long off;
    if (gid < X8) { src = x; dst = g_xh; off = gid; }
    else {
        long w = gid - X8;
        int which = (int)(w / W8); off = w % W8;
        src = (which == 0) ? Wg : (which == 1) ? Wu : Wd;
        dst = (which == 0) ? g_wgh : (which == 1) ? g_wuh : g_wdh;
    }
    float4 v0 = ((const float4*)src)[off*2];
    float4 v1 = ((const float4*)src)[off*2 + 1];
    __half2 h0 = __floats2half2_rn(v0.x, v0.y);
    __half2 h1 = __floats2half2_rn(v0.z, v0.w);
    __half2 h2 = __floats2half2_rn(v1.x, v1.y);
    __half2 h3 = __floats2half2_rn(v1.z, v1.w);
    uint4 o;
    o.x = *(uint32_t*)&h0; o.y = *(uint32_t*)&h1;
    o.z = *(uint32_t*)&h2; o.w = *(uint32_t*)&h3;
    ((uint4*)dst)[off] = o;
    if (gid < NPAD) { g_pair_tok[gid] = 0; g_pair_w[gid] = 0.f; }
    if (gid < NE) g_cnt[gid] = 0;
}

// ---------------- launch #1: router (fp32, unchanged) ----------------
__global__ void router_kernel(const float* __restrict__ x, const float* __restrict__ gw) {
    __shared__ float xs[HD];
    __shared__ float lg[NE];
    int t = blockIdx.x;
    const float4* xv  = (const float4*)(x + (size_t)t * HD);
    float4*       xsv = (float4*)xs;
    for (int i = threadIdx.x; i < HD/4; i += blockDim.x) xsv[i] = xv[i];
    __syncthreads();
    int warp = threadIdx.x >> 5, lane = threadIdx.x & 31;
    for (int e = warp; e < NE; e += 8) {
        const float4* w = (const float4*)(gw + (size_t)e * HD);
        float s = 0.f;
        #pragma unroll 4
        for (int h = lane; h < HD/4; h += 32) {
            float4 wv = w[h]; float4 xr = xsv[h];
            s += wv.x*xr.x + wv.y*xr.y + wv.z*xr.z + wv.w*xr.w;
        }
        #pragma unroll
        for (int o = 16; o; o >>= 1) s += __shfl_xor_sync(0xffffffffu, s, o);
        if (lane == 0) lg[e] = s;
    }
    __syncthreads();
    if (threadIdx.x == 0) {
        int sel[TOPK]; float sv[TOPK];
        unsigned used = 0u;
        #pragma unroll
        for (int k = 0; k < TOPK; k++) {
            float best = -1e30f; int bi = 0;
            for (int e2 = 0; e2 < NE; e2++)
                if (!((used >> e2) & 1u) && lg[e2] > best) { best = lg[e2]; bi = e2; }
            used |= 1u << bi; sel[k] = bi; sv[k] = best;
        }
        float mx = sv[0], den = 0.f, ww[TOPK];
        #pragma unroll
        for (int k = 0; k < TOPK; k++) { ww[k] = expf(sv[k] - mx); den += ww[k]; }
        #pragma unroll
        for (int k = 0; k < TOPK; k++) {
            g_tk_id[t*TOPK + k] = sel[k];
            g_tk_w [t*TOPK + k] = ww[k] / den;
            atomicAdd(&g_cnt[sel[k]], 1);
        }
    }
}

// ---------------- launch #2: scan + pad-tile build + pair fill ----------------
__global__ void scanfill_kernel() {
    __shared__ int scur[NE];
    int tid = threadIdx.x;
    if (tid < 32) {
        int lane = tid;
        int c = (lane < NE) ? g_cnt[lane] : 0;
        int tiles = (c + 127) >> 7;
        int pad = tiles * 128;
        int poff = pad, toff = tiles;
        #pragma unroll
        for (int o = 1; o < 32; o <<= 1) {
            int pv = __shfl_up_sync(0xffffffffu, poff, o);
            int tv = __shfl_up_sync(0xffffffffu, toff, o);
            if (lane >= o) { poff += pv; toff += tv; }
        }
        int pbase = poff - pad, tbase = toff - tiles;
        if (lane < NE) {
            scur[lane] = pbase;
            for (int i = 0; i < tiles; i++) {
                g_tile_e[tbase + i] = lane;
                g_tile_base[tbase + i] = pbase + i*128;
            }
        }
        if (lane == 31) g_ntile = toff;
    }
    __syncthreads();
    for (int p = tid; p < NPAIR; p += 256) {
        int e = g_tk_id[p];
        int pos = atomicAdd(&scur[e], 1);
        g_pair_tok[pos] = p >> 2;
        g_pair_w [pos] = g_tk_w[p];
        g_slot[p] = pos;
    }
}

// ---------------- launch #5: combine ----------------
__global__ void combine_kernel(float* __restrict__ out) {
    int t = blockIdx.x;
    int s0 = g_slot[t*4+0], s1 = g_slot[t*4+1], s2 = g_slot[t*4+2], s3 = g_slot[t*4+3];
    const float4* p0 = (const float4*)(g_pairout + (size_t)s0 * HD);
    const float4* p1 = (const float4*)(g_pairout + (size_t)s1 * HD);
    const float4* p2 = (const float4*)(g_pairout + (size_t)s2 * HD);
    const float4* p3 = (const float4*)(g_pairout + (size_t)s3 * HD);
    float4* o = (float4*)(out + (size_t)t * HD);
    for (int i = threadIdx.x; i < HD/4; i += 256) {
        float4 a = p0[i], b = p1[i], c = p2[i], d = p3[i];
        o[i] = make_float4(a.x+b.x+c.x+d.x, a.y+b.y+c.y+d.y,
                           a.z+b.z+c.z+d.z, a.w+b.w+c.w+d.w);
    }
}

// ---------------- launch #3: stage A — fp16, 256 thr, 2m x 4n, warp m64 x n16L ----------------
__global__ void __launch_bounds__(256, 2)
stageA_kernel() {
    int mt = blockIdx.y;
    if (mt >= g_ntile) return;
    int e = g_tile_e[mt], base = g_tile_base[mt];
    int nb = blockIdx.x;  // 64 logical I cols per block (128 phys: 64 g | 64 u)

    extern __shared__ char smc[];
    float* wts = (float*)(smc + OFF_WTSB);
    uint32_t sAu[2] = { smem_u32(smc), smem_u32(smc) + OFF_SA1B };
    uint32_t sBu[2] = { smem_u32(smc) + OFF_SB0B, smem_u32(smc) + OFF_SB1B };

    int t = threadIdx.x;
    if (t < 128) wts[t] = g_pair_w[base + t];

    // A producer: 128 rows x 32 halves (64B); thread -> (row, 32B half-row): 2x16B
    int arow = t >> 1, aseg = t & 1;
    const __half* asrc0 = g_xh + (size_t)g_pair_tok[base + arow] * HD + aseg * 16;
    uint32_t adst = (uint32_t)(arow * AROWB + aseg * 32);
    // B producer: 32 k-rows x 128 cols halves; thread -> (bk, 8-halves col chunk), 2 k-rows
    int bc = t & 15, bk = t >> 4;
    const __half* wbase = (bc < 8) ? (g_wgh + (size_t)e*HD*ID + (size_t)nb*64 + bc*8)
                                   : (g_wuh + (size_t)e*HD*ID + (size_t)nb*64 + (bc-8)*8);
    const __half* bsrc0 = wbase + (size_t)bk * ID;
    uint32_t bdst = (uint32_t)(bk * BROWB + bc * 16);

    int lane = t & 31, wid = t >> 5;
    int wm  = (wid & 1) * 64;        // 2 m-warp groups
    int wng = (wid >> 1) * 16;       // 4 logical-n warp groups
    int grp = lane >> 2, tg = lane & 3;
    // ldmatrix A address base: row = wm + (lane&15), k-half-block = (lane>>4)*8 halves
    uint32_t aoff = (uint32_t)((wm + (lane & 15)) * AROWB + (lane >> 4) * 16);
    // ldmatrix B address base: k-row = (lane&15)
    uint32_t boff = (uint32_t)((lane & 15) * BROWB);

    float acc[4][4][4];   // [mfrag][n0,n1=g n2,n3=u][frag]
    #pragma unroll
    for (int m = 0; m < 4; m++)
        #pragma unroll
        for (int n = 0; n < 4; n++)
            #pragma unroll
            for (int i = 0; i < 4; i++) acc[m][n][i] = 0.f;

    #pragma unroll
    for (int i = 0; i < 2; i++) cpasync16(sAu[0] + adst + i*16, asrc0 + i*8);
    #pragma unroll
    for (int i = 0; i < 2; i++) cpasync16(sBu[0] + bdst + i*16*BROWB, bsrc0 + (size_t)i*16*ID);
    CP_COMMIT();

    for (int kc = 0; kc < 64; kc++) {
        int b = kc & 1;
        __syncthreads();
        if (kc + 1 < 64) {
            const __half* as = asrc0 + (size_t)(kc+1) * 32;
            const __half* bs = bsrc0 + (size_t)(kc+1) * 32 * ID;
            #pragma unroll
            for (int i = 0; i < 2; i++) cpasync16(sAu[b^1] + adst + i*16, as + i*8);
            #pragma unroll
            for (int i = 0; i < 2; i++) cpasync16(sBu[b^1] + bdst + i*16*BROWB, bs + (size_t)i*16*ID);
            CP_COMMIT();
            CP_WAIT1();
        } else {
            CP_WAIT0();
        }
        __syncthreads();

        uint32_t abase = sAu[b] + aoff;
        uint32_t bbase = sBu[b] + boff;
        #pragma unroll
        for (int ks = 0; ks < 2; ks++) {   // two k16 steps per 32-k chunk
            uint32_t af[4][4];
            #pragma unroll
            for (int m = 0; m < 4; m++)
                LDSM4(af[m][0], af[m][1], af[m][2], af[m][3],
                      abase + m*(16*AROWB) + ks*32);
            uint32_t bf[4][2];
            uint32_t bk16 = bbase + ks*(16*BROWB);
            LDSMT2(bf[0][0], bf[0][1], bk16 + (wng)*2);
            LDSMT2(bf[1][0], bf[1][1], bk16 + (wng+8)*2);
            LDSMT2(bf[2][0], bf[2][1], bk16 + (64+wng)*2);
            LDSMT2(bf[3][0], bf[3][1], bk16 + (64+wng+8)*2);
            #pragma unroll
            for (int nf = 0; nf < 4; nf++)
                #pragma unroll
                for (int m = 0; m < 4; m++)
                    mma16(acc[m][nf], af[m], bf[nf]);
        }
    }

    // epilogue: silu(g)*u*wt -> fp16 store
    #pragma unroll
    for (int m = 0; m < 4; m++) {
        int r0 = wm + m*16 + grp, r1 = r0 + 8;
        float w0 = wts[r0], w1 = wts[r1];
        #pragma unroll
        for (int nf = 0; nf < 2; nf++) {
            int icol = nb*64 + wng + nf*8 + 2*tg;
            float g0 = acc[m][nf][0], g1 = acc[m][nf][1];
            float g2 = acc[m][nf][2], g3 = acc[m][nf][3];
            float u0 = acc[m][nf+2][0], u1 = acc[m][nf+2][1];
            float u2 = acc[m][nf+2][2], u3 = acc[m][nf+2][3];
            float v0 = g0 / (1.f + __expf(-g0)) * u0 * w0;
            float v1 = g1 / (1.f + __expf(-g1)) * u1 * w0;
            float v2 = g2 / (1.f + __expf(-g2)) * u2 * w1;
            float v3 = g3 / (1.f + __expf(-g3)) * u3 * w1;
            *(__half2*)(g_act_h + (size_t)(base + r0) * ID + icol) = __floats2half2_rn(v0, v1);
            *(__half2*)(g_act_h + (size_t)(base + r1) * ID + icol) = __floats2half2_rn(v2, v3);
        }
    }
}

// ---------------- launch #4: stage B — fp16, 256 thr, 2m x 4n, warp m64 x n32 ----------------
__global__ void __launch_bounds__(256, 2)
stageB_kernel() {
    int mt = blockIdx.y;
    if (mt >= g_ntile) return;
    int e = g_tile_e[mt], base = g_tile_base[mt];
    int nb = blockIdx.x;  // 128 HD cols per block

    extern __shared__ char smc[];
    uint32_t sAu[2] = { smem_u32(smc), smem_u32(smc) + OFF_SA1B };
    uint32_t sBu[2] = { smem_u32(smc) + OFF_SB0B, smem_u32(smc) + OFF_SB1B };

    int t = threadIdx.x;
    int arow = t >> 1, aseg = t & 1;
    const __half* asrc0 = g_act_h + (size_t)(base + arow) * ID + aseg * 16;
    uint32_t adst = (uint32_t)(arow * AROWB + aseg * 32);
    int bc = t & 15, bk = t >> 4;
    const __half* bsrc0 = g_wdh + (size_t)e*ID*HD + (size_t)bk*HD + (size_t)nb*128 + bc*8;
    uint32_t bdst = (uint32_t)(bk * BROWB + bc * 16);

    int lane = t & 31, wid = t >> 5;
    int wm = (wid & 1) * 64;
    int wn = (wid >> 1) * 32;
    int grp = lane >> 2, tg = lane & 3;
    uint32_t aoff = (uint32_t)((wm + (lane & 15)) * AROWB + (lane >> 4) * 16);
    uint32_t boff = (uint32_t)((lane & 15) * BROWB);

    float acc[4][4][4];
    #pragma unroll
    for (int m = 0; m < 4; m++)
        #pragma unroll
        for (int n = 0; n < 4; n++)
            #pragma unroll
            for (int i = 0; i < 4; i++) acc[m][n][i] = 0.f;

    #pragma unroll
    for (int i = 0; i < 2; i++) cpasync16(sAu[0] + adst + i*16, asrc0 + i*8);
    #pragma unroll
    for (int i = 0; i < 2; i++) cpasync16(sBu[0] + bdst + i*16*BROWB, bsrc0 + (size_t)i*16*HD);
    CP_COMMIT();

    for (int kc = 0; kc < 24; kc++) {
        int b = kc & 1;
        __syncthreads();
        if (kc + 1 < 24) {
            const __half* as = asrc0 + (size_t)(kc+1) * 32;
            const __half* bs = bsrc0 + (size_t)(kc+1) * 32 * HD;
            #pragma unroll
            for (int i = 0; i < 2; i++) cpasync16(sAu[b^1] + adst + i*16, as + i*8);
            #pragma unroll
            for (int i = 0; i < 2; i++) cpasync16(sBu[b^1] + bdst + i*16*BROWB, bs + (size_t)i*16*HD);
            CP_COMMIT();
            CP_WAIT1();
        } else {
            CP_WAIT0();
        }
        __syncthreads();

        uint32_t abase = sAu[b] + aoff;
        uint32_t bbase = sBu[b] + boff;
        #pragma unroll
        for (int ks = 0; ks < 2; ks++) {
            uint32_t af[4][4];
            #pragma unroll
            for (int m = 0; m < 4; m++)
                LDSM4(af[m][0], af[m][1], af[m][2], af[m][3],
                      abase + m*(16*AROWB) + ks*32);
            uint32_t bf[4][2];
            uint32_t bk16 = bbase + ks*(16*BROWB);
            LDSMT2(bf[0][0], bf[0][1], bk16 + (wn)*2);
            LDSMT2(bf[1][0], bf[1][1], bk16 + (wn+8)*2);
            LDSMT2(bf[2][0], bf[2][1], bk16 + (wn+16)*2);
            LDSMT2(bf[3][0], bf[3][1], bk16 + (wn+24)*2);
            #pragma unroll
            for (int nf = 0; nf < 4; nf++)
                #pragma unroll
                for (int m = 0; m < 4; m++)
                    mma16(acc[m][nf], af[m], bf[nf]);
        }
    }

    #pragma unroll
    for (int m = 0; m < 4; m++) {
        int r0 = wm + m*16 + grp, r1 = r0 + 8;
        #pragma unroll
        for (int nf = 0; nf < 4; nf++) {
            int col = nb*128 + wn + nf*8 + 2*tg;
            *(float2*)(g_pairout + (size_t)(base + r0) * HD + col) =
                make_float2(acc[m][nf][0], acc[m][nf][1]);
            *(float2*)(g_pairout + (size_t)(base + r1) * HD + col) =
                make_float2(acc[m][nf][2], acc[m][nf][3]);
        }
    }
}

// ---------------- launch ----------------
extern "C" void kernel_launch(void* const* d_in, const int* in_sizes, int n_in,
                              void* d_out, int out_size) {
    const float* x  = (const float*)d_in[0];
    const float* gw = (const float*)d_in[1];
    const float* Wg = (const float*)d_in[2];
    const float* Wu = (const float*)d_in[3];
    const float* Wd = (const float*)d_in[4];
    float* out = (float*)d_out;

    cudaFuncSetAttribute(stageA_kernel, cudaFuncAttributeMaxDynamicSharedMemorySize, SM_BYTES);
    cudaFuncSetAttribute(stageB_kernel, cudaFuncAttributeMaxDynamicSharedMemorySize, SM_BYTES);

    // total 8-elem groups: X (524288) + 3 weights (3*6291456) = 19398656 = 75776 * 256
    prep_kernel<<<75776, 256>>>(x, Wg, Wu, Wd);                 // 0
    router_kernel<<<T_TOK, 256>>>(x, gw);                       // 1
    scanfill_kernel<<<1, 256>>>();                              // 2
    stageA_kernel<<<dim3(ID/64, MAXT), 256, SM_BYTES>>>();      // 3 <- profiled by ncu
    stageB_kernel<<<dim3(HD/128, MAXT), 256, SM_BYTES>>>();     // 4
    combine_kernel<<<T_TOK, 256>>>(out);                        // 5
}